// round 4
// baseline (speedup 1.0000x reference)
#include <cuda_runtime.h>
#include <mma.h>
using namespace nvcuda;

#define BATCH 1024
#define EMB   2048
#define NHEAD 32
#define HSZ   64
#define SROWS 66

// ---------------- scratch (no allocations allowed) ----------------
__device__ float g_scr[(size_t)18 * BATCH * EMB];

#define SL_XN   0
#define SL_SX   1
#define SL_XMIX 2
#define SL_XK   3
#define SL_XV   4
#define SL_XR   5
#define SL_XG   6
#define SL_R    7
#define SL_K    8
#define SL_V    9
#define SL_G    10
#define SL_Z    11
#define SL_X1   12
#define SL_XK2  13
#define SL_XR2  14
#define SL_RR   15
#define SL_KK   16
#define SL_T    17

#define EPI_NONE    0
#define EPI_TANH    1
#define EPI_SILU    2
#define EPI_SIGMOID 3
#define EPI_RELUSQ  4
#define EPI_ADDC    5   // out = acc + aux1
#define EPI_MIX     6   // out = aux1 + aux2*(vec1[n] + acc)
#define EPI_FFNOUT  7   // out = aux1 + aux2*acc

// ---------------- 3xTF32 wmma GEMM ----------------
// C[M,N] = A[M,K] @ op(B), fp32-accurate via hi/lo tf32 split:
//   C ≈ Ah*Bh + Ah*Bl + Al*Bh
constexpr int BM = 128, BN = 64, BK = 32;
constexpr int LDA_S  = BK + 4;  // 36
constexpr int LDBT_S = BK + 4;  // 36 ([BN][36])
constexpr int LDBN_S = BN + 4;  // 68 ([BK][68])
constexpr int LDC_S  = BN + 4;  // 68
// dynamic smem floats: Ah+Al (2*128*36=9216) + Bh+Bl (<=2*2304=4608) = 13824
constexpr int SMEM_FLOATS = 2 * BM * LDA_S + 2 * BN * LDBT_S;   // 13824
constexpr size_t SMEM_BYTES = SMEM_FLOATS * sizeof(float);      // 55296

__device__ __forceinline__ void split_tf32(float v, float& h, float& l) {
    h = wmma::__float_to_tf32(v);
    l = wmma::__float_to_tf32(v - h);
}

template<int EPI, bool BT>
__global__ void __launch_bounds__(256)
gemm_k(const float* __restrict__ A, int lda,
       const float* __restrict__ Bw, int ldb,
       float* __restrict__ C, int ldc,
       int M, int N, int K,
       const float* __restrict__ aux1,
       const float* __restrict__ aux2,
       const float* __restrict__ vec1)
{
    extern __shared__ float smem[];
    float* Ah = smem;                       // 128*36
    float* Al = Ah + BM * LDA_S;
    float* Bh = Al + BM * LDA_S;
    float* Bl = Bh + (BT ? BN * LDBT_S : BK * LDBN_S);

    const int tid  = threadIdx.x;
    const int m0   = blockIdx.y * BM;
    const int n0   = blockIdx.x * BN;
    const int w    = tid >> 5;
    const int wm   = (w >> 1) * 32;
    const int wn   = (w & 1) * 32;

    wmma::fragment<wmma::accumulator, 16, 16, 8, float> fc[2][2];
    #pragma unroll
    for (int i = 0; i < 2; i++)
        #pragma unroll
        for (int j = 0; j < 2; j++)
            wmma::fill_fragment(fc[i][j], 0.0f);

    for (int k0 = 0; k0 < K; k0 += BK) {
        // A tile 128x32
        #pragma unroll
        for (int it = 0; it < 4; it++) {
            int idx = tid + it * 256;
            int m   = idx >> 3;
            int kq  = (idx & 7) << 2;
            float4 a4 = *reinterpret_cast<const float4*>(
                &A[(size_t)(m0 + m) * lda + k0 + kq]);
            float h, l;
            split_tf32(a4.x, h, l); Ah[m*LDA_S+kq+0]=h; Al[m*LDA_S+kq+0]=l;
            split_tf32(a4.y, h, l); Ah[m*LDA_S+kq+1]=h; Al[m*LDA_S+kq+1]=l;
            split_tf32(a4.z, h, l); Ah[m*LDA_S+kq+2]=h; Al[m*LDA_S+kq+2]=l;
            split_tf32(a4.w, h, l); Ah[m*LDA_S+kq+3]=h; Al[m*LDA_S+kq+3]=l;
        }
        if (BT) {
            #pragma unroll
            for (int it = 0; it < 2; it++) {
                int idx = tid + it * 256;
                int n   = idx >> 3;
                int kq  = (idx & 7) << 2;
                float4 b4 = *reinterpret_cast<const float4*>(
                    &Bw[(size_t)(n0 + n) * ldb + k0 + kq]);
                float h, l;
                split_tf32(b4.x, h, l); Bh[n*LDBT_S+kq+0]=h; Bl[n*LDBT_S+kq+0]=l;
                split_tf32(b4.y, h, l); Bh[n*LDBT_S+kq+1]=h; Bl[n*LDBT_S+kq+1]=l;
                split_tf32(b4.z, h, l); Bh[n*LDBT_S+kq+2]=h; Bl[n*LDBT_S+kq+2]=l;
                split_tf32(b4.w, h, l); Bh[n*LDBT_S+kq+3]=h; Bl[n*LDBT_S+kq+3]=l;
            }
        } else {
            #pragma unroll
            for (int it = 0; it < 2; it++) {
                int idx = tid + it * 256;
                int k   = idx >> 4;
                int nq  = (idx & 15) << 2;
                float4 b4 = *reinterpret_cast<const float4*>(
                    &Bw[(size_t)(k0 + k) * ldb + n0 + nq]);
                float h, l;
                split_tf32(b4.x, h, l); Bh[k*LDBN_S+nq+0]=h; Bl[k*LDBN_S+nq+0]=l;
                split_tf32(b4.y, h, l); Bh[k*LDBN_S+nq+1]=h; Bl[k*LDBN_S+nq+1]=l;
                split_tf32(b4.z, h, l); Bh[k*LDBN_S+nq+2]=h; Bl[k*LDBN_S+nq+2]=l;
                split_tf32(b4.w, h, l); Bh[k*LDBN_S+nq+3]=h; Bl[k*LDBN_S+nq+3]=l;
            }
        }
        __syncthreads();

        #pragma unroll
        for (int kk8 = 0; kk8 < BK; kk8 += 8) {
            wmma::fragment<wmma::matrix_a, 16, 16, 8, wmma::precision::tf32,
                           wmma::row_major> fah[2], fal[2];
            #pragma unroll
            for (int i = 0; i < 2; i++) {
                wmma::load_matrix_sync(fah[i], &Ah[(wm + i*16) * LDA_S + kk8], LDA_S);
                wmma::load_matrix_sync(fal[i], &Al[(wm + i*16) * LDA_S + kk8], LDA_S);
            }
            if (BT) {
                wmma::fragment<wmma::matrix_b, 16, 16, 8, wmma::precision::tf32,
                               wmma::col_major> fbh[2], fbl[2];
                #pragma unroll
                for (int j = 0; j < 2; j++) {
                    wmma::load_matrix_sync(fbh[j], &Bh[(wn + j*16) * LDBT_S + kk8], LDBT_S);
                    wmma::load_matrix_sync(fbl[j], &Bl[(wn + j*16) * LDBT_S + kk8], LDBT_S);
                }
                #pragma unroll
                for (int i = 0; i < 2; i++)
                    #pragma unroll
                    for (int j = 0; j < 2; j++) {
                        wmma::mma_sync(fc[i][j], fal[i], fbh[j], fc[i][j]);
                        wmma::mma_sync(fc[i][j], fah[i], fbl[j], fc[i][j]);
                        wmma::mma_sync(fc[i][j], fah[i], fbh[j], fc[i][j]);
                    }
            } else {
                wmma::fragment<wmma::matrix_b, 16, 16, 8, wmma::precision::tf32,
                               wmma::row_major> fbh[2], fbl[2];
                #pragma unroll
                for (int j = 0; j < 2; j++) {
                    wmma::load_matrix_sync(fbh[j], &Bh[kk8 * LDBN_S + wn + j*16], LDBN_S);
                    wmma::load_matrix_sync(fbl[j], &Bl[kk8 * LDBN_S + wn + j*16], LDBN_S);
                }
                #pragma unroll
                for (int i = 0; i < 2; i++)
                    #pragma unroll
                    for (int j = 0; j < 2; j++) {
                        wmma::mma_sync(fc[i][j], fal[i], fbh[j], fc[i][j]);
                        wmma::mma_sync(fc[i][j], fah[i], fbl[j], fc[i][j]);
                        wmma::mma_sync(fc[i][j], fah[i], fbh[j], fc[i][j]);
                    }
            }
        }
        __syncthreads();
    }

    // C tile via smem (reuse)
    #pragma unroll
    for (int i = 0; i < 2; i++)
        #pragma unroll
        for (int j = 0; j < 2; j++)
            wmma::store_matrix_sync(&smem[(wm + i*16) * LDC_S + wn + j*16],
                                    fc[i][j], LDC_S, wmma::mem_row_major);
    __syncthreads();

    #pragma unroll
    for (int it = 0; it < 32; it++) {
        int idx = tid + it * 256;
        int m   = idx >> 6;
        int n   = idx & 63;
        float acc = smem[m * LDC_S + n];
        size_t gi = (size_t)(m0 + m) * ldc + n0 + n;
        float o;
        if (EPI == EPI_NONE)        o = acc;
        else if (EPI == EPI_TANH)   o = tanhf(acc);
        else if (EPI == EPI_SILU)   o = acc / (1.0f + __expf(-acc));
        else if (EPI == EPI_SIGMOID) o = 1.0f / (1.0f + __expf(-acc));
        else if (EPI == EPI_RELUSQ) { float rv = fmaxf(acc, 0.0f); o = rv * rv; }
        else if (EPI == EPI_ADDC)   o = acc + aux1[gi];
        else if (EPI == EPI_MIX)    o = aux1[gi] + aux2[gi] * (vec1[n0 + n] + acc);
        else /* EPI_FFNOUT */       o = aux1[gi] + aux2[gi] * acc;
        C[gi] = o;
    }
}

// ---------------- ln + token-shift fuse (time mix) ----------------
__global__ void __launch_bounds__(256)
ln_mix1(const float* __restrict__ x, const float* __restrict__ state,
        const float* __restrict__ lnw, const float* __restrict__ lnb,
        const float* __restrict__ maa_x,
        float* __restrict__ xn_o, float* __restrict__ sx_o,
        float* __restrict__ xmix_o)
{
    int b = blockIdx.x;
    const float* xr = x + (size_t)b * EMB;
    float v[8]; float s = 0.f, sq = 0.f;
    #pragma unroll
    for (int i = 0; i < 8; i++) {
        v[i] = xr[threadIdx.x + i * 256];
        s += v[i]; sq += v[i] * v[i];
    }
    __shared__ float red[16];
    #pragma unroll
    for (int o = 16; o > 0; o >>= 1) {
        s  += __shfl_down_sync(0xffffffffu, s,  o);
        sq += __shfl_down_sync(0xffffffffu, sq, o);
    }
    int w = threadIdx.x >> 5;
    if ((threadIdx.x & 31) == 0) { red[w] = s; red[w + 8] = sq; }
    __syncthreads();
    if (threadIdx.x == 0) {
        float ts = 0.f, tq = 0.f;
        for (int i = 0; i < 8; i++) { ts += red[i]; tq += red[i + 8]; }
        red[0] = ts; red[8] = tq;
    }
    __syncthreads();
    float mu  = red[0] * (1.0f / EMB);
    float var = red[8] * (1.0f / EMB) - mu * mu;
    float rs  = rsqrtf(var + 1e-5f);
    const float* srow = state + ((size_t)b * SROWS + 1) * EMB;
    #pragma unroll
    for (int i = 0; i < 8; i++) {
        int e = threadIdx.x + i * 256;
        float xnv = (v[i] - mu) * rs * lnw[e] + lnb[e];
        float sxv = srow[e] - xnv;
        size_t gi = (size_t)b * EMB + e;
        xn_o[gi] = xnv;
        sx_o[gi] = sxv;
        xmix_o[gi] = xnv + sxv * maa_x[e];
    }
}

// ---------------- ln + token-shift fuse (channel mix) ----------------
__global__ void __launch_bounds__(256)
ln_mix2(const float* __restrict__ x1, const float* __restrict__ state,
        const float* __restrict__ lnw, const float* __restrict__ lnb,
        const float* __restrict__ maa_k, const float* __restrict__ maa_r,
        float* __restrict__ xk_o, float* __restrict__ xr_o)
{
    int b = blockIdx.x;
    const float* xr = x1 + (size_t)b * EMB;
    float v[8]; float s = 0.f, sq = 0.f;
    #pragma unroll
    for (int i = 0; i < 8; i++) {
        v[i] = xr[threadIdx.x + i * 256];
        s += v[i]; sq += v[i] * v[i];
    }
    __shared__ float red[16];
    #pragma unroll
    for (int o = 16; o > 0; o >>= 1) {
        s  += __shfl_down_sync(0xffffffffu, s,  o);
        sq += __shfl_down_sync(0xffffffffu, sq, o);
    }
    int w = threadIdx.x >> 5;
    if ((threadIdx.x & 31) == 0) { red[w] = s; red[w + 8] = sq; }
    __syncthreads();
    if (threadIdx.x == 0) {
        float ts = 0.f, tq = 0.f;
        for (int i = 0; i < 8; i++) { ts += red[i]; tq += red[i + 8]; }
        red[0] = ts; red[8] = tq;
    }
    __syncthreads();
    float mu  = red[0] * (1.0f / EMB);
    float var = red[8] * (1.0f / EMB) - mu * mu;
    float rs  = rsqrtf(var + 1e-5f);
    const float* srow = state + (size_t)b * SROWS * EMB;  // row 0
    #pragma unroll
    for (int i = 0; i < 8; i++) {
        int e = threadIdx.x + i * 256;
        float xnv = (v[i] - mu) * rs * lnw[e] + lnb[e];
        float sxv = srow[e] - xnv;
        size_t gi = (size_t)b * EMB + e;
        xk_o[gi] = xnv + sxv * maa_k[e];
        xr_o[gi] = xnv + sxv * maa_r[e];
    }
}

// ---------------- wkv readout + groupnorm + (pre-silu'ed) gate ----------------
__global__ void __launch_bounds__(64)
wkv_gn(const float* __restrict__ r, const float* __restrict__ k,
       const float* __restrict__ v, const float* __restrict__ gp,
       const float* __restrict__ state, const float* __restrict__ faaaa,
       const float* __restrict__ gnw, const float* __restrict__ gnb,
       float* __restrict__ z)
{
    int bh = blockIdx.x;
    int b  = bh >> 5;
    int h  = bh & 31;
    int j  = threadIdx.x;  // 0..63
    size_t off = (size_t)b * EMB + h * 64 + j;
    float rv = r[off], kv = k[off], vv = v[off];
    float fv = faaaa[h * 64 + j];

    __shared__ float rs_sh[64];
    __shared__ float red1[2];
    __shared__ float red2[4];
    rs_sh[j] = rv;

    float p = rv * fv * kv;
    #pragma unroll
    for (int o = 16; o > 0; o >>= 1) p += __shfl_down_sync(0xffffffffu, p, o);
    int w = j >> 5;
    if ((j & 31) == 0) red1[w] = p;
    __syncthreads();
    float coef = red1[0] + red1[1];

    const float* sb = state + ((size_t)b * SROWS + 2 + 2 * h) * EMB;
    float acc = 0.f;
    #pragma unroll
    for (int i = 0; i < 64; i++)
        acc += rs_sh[i] * sb[(i >> 5) * EMB + ((i & 31) << 6) + j];

    float y = coef * vv + acc;

    float s = y, sq = y * y;
    #pragma unroll
    for (int o = 16; o > 0; o >>= 1) {
        s  += __shfl_down_sync(0xffffffffu, s,  o);
        sq += __shfl_down_sync(0xffffffffu, sq, o);
    }
    if ((j & 31) == 0) { red2[w] = s; red2[2 + w] = sq; }
    __syncthreads();
    float mu  = (red2[0] + red2[1]) * (1.0f / 64.0f);
    float var = (red2[2] + red2[3]) * (1.0f / 64.0f) - mu * mu;
    float zn  = (y - mu) * rsqrtf(var + 1e-5f) * gnw[h * 64 + j] + gnb[h * 64 + j];
    // gp is ALREADY silu(xg@Wg.T) — do NOT re-apply silu (round-1 bug).
    z[off] = zn * gp[off];
}

// ---------------- launch ----------------
extern "C" void kernel_launch(void* const* d_in, const int* in_sizes, int n_in,
                              void* d_out, int out_size)
{
    (void)in_sizes; (void)n_in; (void)out_size;
    const float* x       = (const float*)d_in[0];
    const float* state   = (const float*)d_in[1];
    const float* ln1_w   = (const float*)d_in[2];
    const float* ln1_b   = (const float*)d_in[3];
    const float* ln2_w   = (const float*)d_in[4];
    const float* ln2_b   = (const float*)d_in[5];
    const float* maa_x   = (const float*)d_in[6];
    const float* maa_k   = (const float*)d_in[8];
    const float* maa_v   = (const float*)d_in[9];
    const float* maa_r   = (const float*)d_in[10];
    const float* maa_g   = (const float*)d_in[11];
    const float* maa_w1  = (const float*)d_in[12];  // [E, 320]
    const float* maa_w2  = (const float*)d_in[13];  // [5, 64, E]
    const float* faaaa   = (const float*)d_in[17];  // [H, 64]
    const float* Wr      = (const float*)d_in[18];
    const float* Wk      = (const float*)d_in[19];
    const float* Wv      = (const float*)d_in[20];
    const float* Wo      = (const float*)d_in[21];
    const float* Wg      = (const float*)d_in[22];
    const float* gn_w    = (const float*)d_in[23];
    const float* gn_b    = (const float*)d_in[24];
    const float* f_maa_k = (const float*)d_in[25];
    const float* f_maa_r = (const float*)d_in[26];
    const float* ffn_Wk  = (const float*)d_in[27];
    const float* ffn_Wr  = (const float*)d_in[28];
    const float* ffn_Wv  = (const float*)d_in[29];
    float* out = (float*)d_out;

    // raise dynamic smem limit for all instantiations (host-side, capture-safe)
    cudaFuncSetAttribute(gemm_k<EPI_TANH,   false>, cudaFuncAttributeMaxDynamicSharedMemorySize, (int)SMEM_BYTES);
    cudaFuncSetAttribute(gemm_k<EPI_MIX,    false>, cudaFuncAttributeMaxDynamicSharedMemorySize, (int)SMEM_BYTES);
    cudaFuncSetAttribute(gemm_k<EPI_NONE,   true >, cudaFuncAttributeMaxDynamicSharedMemorySize, (int)SMEM_BYTES);
    cudaFuncSetAttribute(gemm_k<EPI_SILU,   true >, cudaFuncAttributeMaxDynamicSharedMemorySize, (int)SMEM_BYTES);
    cudaFuncSetAttribute(gemm_k<EPI_ADDC,   true >, cudaFuncAttributeMaxDynamicSharedMemorySize, (int)SMEM_BYTES);
    cudaFuncSetAttribute(gemm_k<EPI_SIGMOID,true >, cudaFuncAttributeMaxDynamicSharedMemorySize, (int)SMEM_BYTES);
    cudaFuncSetAttribute(gemm_k<EPI_RELUSQ, true >, cudaFuncAttributeMaxDynamicSharedMemorySize, (int)SMEM_BYTES);
    cudaFuncSetAttribute(gemm_k<EPI_FFNOUT, true >, cudaFuncAttributeMaxDynamicSharedMemorySize, (int)SMEM_BYTES);

    float* scr = nullptr;
    cudaGetSymbolAddress((void**)&scr, g_scr);
    auto S = [&](int i) { return scr + (size_t)i * BATCH * EMB; };
    float *xn = S(SL_XN), *sx = S(SL_SX), *xmix = S(SL_XMIX);
    float *xk = S(SL_XK), *xv = S(SL_XV), *xrb = S(SL_XR), *xg = S(SL_XG);
    float *rb = S(SL_R), *kb = S(SL_K), *vb = S(SL_V), *gb = S(SL_G);
    float *zb = S(SL_Z), *x1 = S(SL_X1);
    float *xk2 = S(SL_XK2), *xr2 = S(SL_XR2);
    float *rr = S(SL_RR), *kk = S(SL_KK), *tb = S(SL_T);

    dim3 blk(256);
    dim3 gE(EMB / BN, BATCH / BM);      // 32 x 8
    dim3 gT(320 / BN, BATCH / BM);      // 5 x 8

    // 1) ln1 + token-shift + maa_x premix
    ln_mix1<<<BATCH, blk>>>(x, state, ln1_w, ln1_b, maa_x, xn, sx, xmix);

    // 2) t = tanh(xmix @ maa_w1)   [B, 320]
    gemm_k<EPI_TANH, false><<<gT, blk, SMEM_BYTES>>>(xmix, EMB, maa_w1, 320, tb, 320,
                                         BATCH, 320, EMB, nullptr, nullptr, nullptr);

    // 3) mix lanes k, v, r, g  (lane 0 / decay path is dead code)
    gemm_k<EPI_MIX, false><<<gE, blk, SMEM_BYTES>>>(tb + 64*1, 320, maa_w2 + (size_t)1*64*EMB, EMB,
                                        xk, EMB, BATCH, EMB, 64, xn, sx, maa_k);
    gemm_k<EPI_MIX, false><<<gE, blk, SMEM_BYTES>>>(tb + 64*2, 320, maa_w2 + (size_t)2*64*EMB, EMB,
                                        xv, EMB, BATCH, EMB, 64, xn, sx, maa_v);
    gemm_k<EPI_MIX, false><<<gE, blk, SMEM_BYTES>>>(tb + 64*3, 320, maa_w2 + (size_t)3*64*EMB, EMB,
                                        xrb, EMB, BATCH, EMB, 64, xn, sx, maa_r);
    gemm_k<EPI_MIX, false><<<gE, blk, SMEM_BYTES>>>(tb + 64*4, 320, maa_w2 + (size_t)4*64*EMB, EMB,
                                        xg, EMB, BATCH, EMB, 64, xn, sx, maa_g);

    // 4) projections
    gemm_k<EPI_NONE, true><<<gE, blk, SMEM_BYTES>>>(xrb, EMB, Wr, EMB, rb, EMB,
                                        BATCH, EMB, EMB, nullptr, nullptr, nullptr);
    gemm_k<EPI_NONE, true><<<gE, blk, SMEM_BYTES>>>(xk, EMB, Wk, EMB, kb, EMB,
                                        BATCH, EMB, EMB, nullptr, nullptr, nullptr);
    gemm_k<EPI_NONE, true><<<gE, blk, SMEM_BYTES>>>(xv, EMB, Wv, EMB, vb, EMB,
                                        BATCH, EMB, EMB, nullptr, nullptr, nullptr);
    gemm_k<EPI_SILU, true><<<gE, blk, SMEM_BYTES>>>(xg, EMB, Wg, EMB, gb, EMB,
                                        BATCH, EMB, EMB, nullptr, nullptr, nullptr);

    // 5) wkv readout + groupnorm + gate
    wkv_gn<<<BATCH * NHEAD, 64>>>(rb, kb, vb, gb, state, faaaa, gn_w, gn_b, zb);

    // 6) x1 = x + z @ Wo^T
    gemm_k<EPI_ADDC, true><<<gE, blk, SMEM_BYTES>>>(zb, EMB, Wo, EMB, x1, EMB,
                                        BATCH, EMB, EMB, x, nullptr, nullptr);

    // 7) channel mix
    ln_mix2<<<BATCH, blk>>>(x1, state, ln2_w, ln2_b, f_maa_k, f_maa_r, xk2, xr2);
    gemm_k<EPI_SIGMOID, true><<<gE, blk, SMEM_BYTES>>>(xr2, EMB, ffn_Wr, EMB, rr, EMB,
                                           BATCH, EMB, EMB, nullptr, nullptr, nullptr);
    gemm_k<EPI_RELUSQ, true><<<gE, blk, SMEM_BYTES>>>(xk2, EMB, ffn_Wk, EMB, kk, EMB,
                                          BATCH, EMB, EMB, nullptr, nullptr, nullptr);
    // 8) out = x1 + rr * (kk @ ffn_Wv^T)
    gemm_k<EPI_FFNOUT, true><<<gE, blk, SMEM_BYTES>>>(kk, EMB, ffn_Wv, EMB, out, EMB,
                                          BATCH, EMB, EMB, x1, rr, nullptr);
}

// round 5
// speedup vs baseline: 1.1402x; 1.1402x over previous
#include <cuda_runtime.h>
#include <mma.h>
using namespace nvcuda;

#define BATCH 1024
#define EMB   2048
#define NHEAD 32
#define HSZ   64
#define SROWS 66

// ---------------- scratch (no allocations allowed) ----------------
__device__ float g_scr[(size_t)18 * BATCH * EMB];

#define SL_XN   0
#define SL_SX   1
#define SL_XMIX 2
#define SL_XK   3
#define SL_XV   4
#define SL_XR   5
#define SL_XG   6
#define SL_R    7
#define SL_K    8
#define SL_V    9
#define SL_G    10
#define SL_Z    11
#define SL_X1   12
#define SL_XK2  13
#define SL_XR2  14
#define SL_RR   15
#define SL_KK   16
#define SL_T    17

#define EPI_NONE    0
#define EPI_TANH    1
#define EPI_SILU    2
#define EPI_SIGMOID 3
#define EPI_RELUSQ  4
#define EPI_ADDC    5   // out = acc + aux1
#define EPI_MIX     6   // out = aux1 + aux2*(vec1[n] + acc)
#define EPI_FFNOUT  7   // out = aux1 + aux2*acc

// ---------------- 3xTF32 wmma GEMM, register-staged pipeline ----------------
// C[M,N] = A[M,K] @ op(B); C ≈ Ah*Bh + Ah*Bl + Al*Bh (fp32-accurate)
constexpr int BM = 128, BN = 64, BK = 32;
constexpr int LDA_S  = BK + 4;  // 36
constexpr int LDBT_S = BK + 4;  // 36 ([BN][36])
constexpr int LDBN_S = BN + 4;  // 68 ([BK][68])
constexpr int LDC_S  = BN + 4;  // 68
constexpr int SMEM_FLOATS = 2 * BM * LDA_S + 2 * BN * LDBT_S;   // 13824
constexpr size_t SMEM_BYTES = SMEM_FLOATS * sizeof(float);      // 55296

__device__ __forceinline__ void split_tf32(float v, float& h, float& l) {
    h = wmma::__float_to_tf32(v);
    l = wmma::__float_to_tf32(v - h);
}

template<int EPI, bool BT>
__global__ void __launch_bounds__(256, 2)
gemm_k(const float* __restrict__ A, int lda,
       const float* __restrict__ Bw, int ldb,
       float* __restrict__ C, int ldc,
       int M, int N, int K,
       const float* __restrict__ aux1,
       const float* __restrict__ aux2,
       const float* __restrict__ vec1)
{
    extern __shared__ float smem[];
    float* Ah = smem;                       // 128*36
    float* Al = Ah + BM * LDA_S;
    float* Bh = Al + BM * LDA_S;
    float* Bl = Bh + (BT ? BN * LDBT_S : BK * LDBN_S);

    const int tid  = threadIdx.x;
    const int m0   = blockIdx.y * BM;
    const int n0   = blockIdx.x * BN;
    const int w    = tid >> 5;
    const int wm   = (w >> 1) * 32;
    const int wn   = (w & 1) * 32;

    // register staging for global->smem pipeline
    float rA[16];
    float rB[8];

    auto load_tiles = [&](int k0) {
        #pragma unroll
        for (int it = 0; it < 4; it++) {
            int idx = tid + it * 256;
            int m   = idx >> 3;
            int kq  = (idx & 7) << 2;
            float4 a4 = *reinterpret_cast<const float4*>(
                &A[(size_t)(m0 + m) * lda + k0 + kq]);
            rA[it*4+0] = a4.x; rA[it*4+1] = a4.y;
            rA[it*4+2] = a4.z; rA[it*4+3] = a4.w;
        }
        if (BT) {
            #pragma unroll
            for (int it = 0; it < 2; it++) {
                int idx = tid + it * 256;
                int n   = idx >> 3;
                int kq  = (idx & 7) << 2;
                float4 b4 = *reinterpret_cast<const float4*>(
                    &Bw[(size_t)(n0 + n) * ldb + k0 + kq]);
                rB[it*4+0] = b4.x; rB[it*4+1] = b4.y;
                rB[it*4+2] = b4.z; rB[it*4+3] = b4.w;
            }
        } else {
            #pragma unroll
            for (int it = 0; it < 2; it++) {
                int idx = tid + it * 256;
                int k   = idx >> 4;
                int nq  = (idx & 15) << 2;
                float4 b4 = *reinterpret_cast<const float4*>(
                    &Bw[(size_t)(k0 + k) * ldb + n0 + nq]);
                rB[it*4+0] = b4.x; rB[it*4+1] = b4.y;
                rB[it*4+2] = b4.z; rB[it*4+3] = b4.w;
            }
        }
    };

    auto store_tiles = [&]() {
        #pragma unroll
        for (int it = 0; it < 4; it++) {
            int idx = tid + it * 256;
            int m   = idx >> 3;
            int kq  = (idx & 7) << 2;
            #pragma unroll
            for (int q = 0; q < 4; q++) {
                float h, l; split_tf32(rA[it*4+q], h, l);
                Ah[m*LDA_S+kq+q] = h; Al[m*LDA_S+kq+q] = l;
            }
        }
        if (BT) {
            #pragma unroll
            for (int it = 0; it < 2; it++) {
                int idx = tid + it * 256;
                int n   = idx >> 3;
                int kq  = (idx & 7) << 2;
                #pragma unroll
                for (int q = 0; q < 4; q++) {
                    float h, l; split_tf32(rB[it*4+q], h, l);
                    Bh[n*LDBT_S+kq+q] = h; Bl[n*LDBT_S+kq+q] = l;
                }
            }
        } else {
            #pragma unroll
            for (int it = 0; it < 2; it++) {
                int idx = tid + it * 256;
                int k   = idx >> 4;
                int nq  = (idx & 15) << 2;
                #pragma unroll
                for (int q = 0; q < 4; q++) {
                    float h, l; split_tf32(rB[it*4+q], h, l);
                    Bh[k*LDBN_S+nq+q] = h; Bl[k*LDBN_S+nq+q] = l;
                }
            }
        }
    };

    wmma::fragment<wmma::accumulator, 16, 16, 8, float> fc[2][2];
    #pragma unroll
    for (int i = 0; i < 2; i++)
        #pragma unroll
        for (int j = 0; j < 2; j++)
            wmma::fill_fragment(fc[i][j], 0.0f);

    load_tiles(0);   // prologue

    for (int k0 = 0; k0 < K; k0 += BK) {
        __syncthreads();     // prior MMAs done reading smem
        store_tiles();
        __syncthreads();     // tiles visible
        if (k0 + BK < K) load_tiles(k0 + BK);   // overlap with MMAs below

        #pragma unroll
        for (int kk8 = 0; kk8 < BK; kk8 += 8) {
            wmma::fragment<wmma::matrix_a, 16, 16, 8, wmma::precision::tf32,
                           wmma::row_major> fah[2], fal[2];
            #pragma unroll
            for (int i = 0; i < 2; i++) {
                wmma::load_matrix_sync(fah[i], &Ah[(wm + i*16) * LDA_S + kk8], LDA_S);
                wmma::load_matrix_sync(fal[i], &Al[(wm + i*16) * LDA_S + kk8], LDA_S);
            }
            if (BT) {
                wmma::fragment<wmma::matrix_b, 16, 16, 8, wmma::precision::tf32,
                               wmma::col_major> fbh[2], fbl[2];
                #pragma unroll
                for (int j = 0; j < 2; j++) {
                    wmma::load_matrix_sync(fbh[j], &Bh[(wn + j*16) * LDBT_S + kk8], LDBT_S);
                    wmma::load_matrix_sync(fbl[j], &Bl[(wn + j*16) * LDBT_S + kk8], LDBT_S);
                }
                #pragma unroll
                for (int i = 0; i < 2; i++)
                    #pragma unroll
                    for (int j = 0; j < 2; j++) {
                        wmma::mma_sync(fc[i][j], fal[i], fbh[j], fc[i][j]);
                        wmma::mma_sync(fc[i][j], fah[i], fbl[j], fc[i][j]);
                        wmma::mma_sync(fc[i][j], fah[i], fbh[j], fc[i][j]);
                    }
            } else {
                wmma::fragment<wmma::matrix_b, 16, 16, 8, wmma::precision::tf32,
                               wmma::row_major> fbh[2], fbl[2];
                #pragma unroll
                for (int j = 0; j < 2; j++) {
                    wmma::load_matrix_sync(fbh[j], &Bh[kk8 * LDBN_S + wn + j*16], LDBN_S);
                    wmma::load_matrix_sync(fbl[j], &Bl[kk8 * LDBN_S + wn + j*16], LDBN_S);
                }
                #pragma unroll
                for (int i = 0; i < 2; i++)
                    #pragma unroll
                    for (int j = 0; j < 2; j++) {
                        wmma::mma_sync(fc[i][j], fal[i], fbh[j], fc[i][j]);
                        wmma::mma_sync(fc[i][j], fah[i], fbl[j], fc[i][j]);
                        wmma::mma_sync(fc[i][j], fah[i], fbh[j], fc[i][j]);
                    }
            }
        }
    }
    __syncthreads();

    // C tile via smem (reuse)
    #pragma unroll
    for (int i = 0; i < 2; i++)
        #pragma unroll
        for (int j = 0; j < 2; j++)
            wmma::store_matrix_sync(&smem[(wm + i*16) * LDC_S + wn + j*16],
                                    fc[i][j], LDC_S, wmma::mem_row_major);
    __syncthreads();

    #pragma unroll
    for (int it = 0; it < 32; it++) {
        int idx = tid + it * 256;
        int m   = idx >> 6;
        int n   = idx & 63;
        float acc = smem[m * LDC_S + n];
        size_t gi = (size_t)(m0 + m) * ldc + n0 + n;
        float o;
        if (EPI == EPI_NONE)        o = acc;
        else if (EPI == EPI_TANH)   o = tanhf(acc);
        else if (EPI == EPI_SILU)   o = acc / (1.0f + __expf(-acc));
        else if (EPI == EPI_SIGMOID) o = 1.0f / (1.0f + __expf(-acc));
        else if (EPI == EPI_RELUSQ) { float rv = fmaxf(acc, 0.0f); o = rv * rv; }
        else if (EPI == EPI_ADDC)   o = acc + aux1[gi];
        else if (EPI == EPI_MIX)    o = aux1[gi] + aux2[gi] * (vec1[n0 + n] + acc);
        else /* EPI_FFNOUT */       o = aux1[gi] + aux2[gi] * acc;
        C[gi] = o;
    }
}

// ---------------- ln + token-shift fuse (time mix) ----------------
__global__ void __launch_bounds__(256)
ln_mix1(const float* __restrict__ x, const float* __restrict__ state,
        const float* __restrict__ lnw, const float* __restrict__ lnb,
        const float* __restrict__ maa_x,
        float* __restrict__ xn_o, float* __restrict__ sx_o,
        float* __restrict__ xmix_o)
{
    int b = blockIdx.x;
    const float* xr = x + (size_t)b * EMB;
    float v[8]; float s = 0.f, sq = 0.f;
    #pragma unroll
    for (int i = 0; i < 8; i++) {
        v[i] = xr[threadIdx.x + i * 256];
        s += v[i]; sq += v[i] * v[i];
    }
    __shared__ float red[16];
    #pragma unroll
    for (int o = 16; o > 0; o >>= 1) {
        s  += __shfl_down_sync(0xffffffffu, s,  o);
        sq += __shfl_down_sync(0xffffffffu, sq, o);
    }
    int w = threadIdx.x >> 5;
    if ((threadIdx.x & 31) == 0) { red[w] = s; red[w + 8] = sq; }
    __syncthreads();
    if (threadIdx.x == 0) {
        float ts = 0.f, tq = 0.f;
        for (int i = 0; i < 8; i++) { ts += red[i]; tq += red[i + 8]; }
        red[0] = ts; red[8] = tq;
    }
    __syncthreads();
    float mu  = red[0] * (1.0f / EMB);
    float var = red[8] * (1.0f / EMB) - mu * mu;
    float rs  = rsqrtf(var + 1e-5f);
    const float* srow = state + ((size_t)b * SROWS + 1) * EMB;
    #pragma unroll
    for (int i = 0; i < 8; i++) {
        int e = threadIdx.x + i * 256;
        float xnv = (v[i] - mu) * rs * lnw[e] + lnb[e];
        float sxv = srow[e] - xnv;
        size_t gi = (size_t)b * EMB + e;
        xn_o[gi] = xnv;
        sx_o[gi] = sxv;
        xmix_o[gi] = xnv + sxv * maa_x[e];
    }
}

// ---------------- ln + token-shift fuse (channel mix) ----------------
__global__ void __launch_bounds__(256)
ln_mix2(const float* __restrict__ x1, const float* __restrict__ state,
        const float* __restrict__ lnw, const float* __restrict__ lnb,
        const float* __restrict__ maa_k, const float* __restrict__ maa_r,
        float* __restrict__ xk_o, float* __restrict__ xr_o)
{
    int b = blockIdx.x;
    const float* xr = x1 + (size_t)b * EMB;
    float v[8]; float s = 0.f, sq = 0.f;
    #pragma unroll
    for (int i = 0; i < 8; i++) {
        v[i] = xr[threadIdx.x + i * 256];
        s += v[i]; sq += v[i] * v[i];
    }
    __shared__ float red[16];
    #pragma unroll
    for (int o = 16; o > 0; o >>= 1) {
        s  += __shfl_down_sync(0xffffffffu, s,  o);
        sq += __shfl_down_sync(0xffffffffu, sq, o);
    }
    int w = threadIdx.x >> 5;
    if ((threadIdx.x & 31) == 0) { red[w] = s; red[w + 8] = sq; }
    __syncthreads();
    if (threadIdx.x == 0) {
        float ts = 0.f, tq = 0.f;
        for (int i = 0; i < 8; i++) { ts += red[i]; tq += red[i + 8]; }
        red[0] = ts; red[8] = tq;
    }
    __syncthreads();
    float mu  = red[0] * (1.0f / EMB);
    float var = red[8] * (1.0f / EMB) - mu * mu;
    float rs  = rsqrtf(var + 1e-5f);
    const float* srow = state + (size_t)b * SROWS * EMB;  // row 0
    #pragma unroll
    for (int i = 0; i < 8; i++) {
        int e = threadIdx.x + i * 256;
        float xnv = (v[i] - mu) * rs * lnw[e] + lnb[e];
        float sxv = srow[e] - xnv;
        size_t gi = (size_t)b * EMB + e;
        xk_o[gi] = xnv + sxv * maa_k[e];
        xr_o[gi] = xnv + sxv * maa_r[e];
    }
}

// ---------------- wkv readout + groupnorm + (pre-silu'ed) gate ----------------
__global__ void __launch_bounds__(64)
wkv_gn(const float* __restrict__ r, const float* __restrict__ k,
       const float* __restrict__ v, const float* __restrict__ gp,
       const float* __restrict__ state, const float* __restrict__ faaaa,
       const float* __restrict__ gnw, const float* __restrict__ gnb,
       float* __restrict__ z)
{
    int bh = blockIdx.x;
    int b  = bh >> 5;
    int h  = bh & 31;
    int j  = threadIdx.x;  // 0..63
    size_t off = (size_t)b * EMB + h * 64 + j;
    float rv = r[off], kv = k[off], vv = v[off];
    float fv = faaaa[h * 64 + j];

    __shared__ float rs_sh[64];
    __shared__ float red1[2];
    __shared__ float red2[4];
    rs_sh[j] = rv;

    float p = rv * fv * kv;
    #pragma unroll
    for (int o = 16; o > 0; o >>= 1) p += __shfl_down_sync(0xffffffffu, p, o);
    int w = j >> 5;
    if ((j & 31) == 0) red1[w] = p;
    __syncthreads();
    float coef = red1[0] + red1[1];

    const float* sb = state + ((size_t)b * SROWS + 2 + 2 * h) * EMB;
    float acc = 0.f;
    #pragma unroll
    for (int i = 0; i < 64; i++)
        acc += rs_sh[i] * sb[(i >> 5) * EMB + ((i & 31) << 6) + j];

    float y = coef * vv + acc;

    float s = y, sq = y * y;
    #pragma unroll
    for (int o = 16; o > 0; o >>= 1) {
        s  += __shfl_down_sync(0xffffffffu, s,  o);
        sq += __shfl_down_sync(0xffffffffu, sq, o);
    }
    if ((j & 31) == 0) { red2[w] = s; red2[2 + w] = sq; }
    __syncthreads();
    float mu  = (red2[0] + red2[1]) * (1.0f / 64.0f);
    float var = (red2[2] + red2[3]) * (1.0f / 64.0f) - mu * mu;
    float zn  = (y - mu) * rsqrtf(var + 1e-5f) * gnw[h * 64 + j] + gnb[h * 64 + j];
    // gp is ALREADY silu(xg@Wg.T) — do NOT re-apply silu.
    z[off] = zn * gp[off];
}

// ---------------- launch ----------------
extern "C" void kernel_launch(void* const* d_in, const int* in_sizes, int n_in,
                              void* d_out, int out_size)
{
    (void)in_sizes; (void)n_in; (void)out_size;
    const float* x       = (const float*)d_in[0];
    const float* state   = (const float*)d_in[1];
    const float* ln1_w   = (const float*)d_in[2];
    const float* ln1_b   = (const float*)d_in[3];
    const float* ln2_w   = (const float*)d_in[4];
    const float* ln2_b   = (const float*)d_in[5];
    const float* maa_x   = (const float*)d_in[6];
    const float* maa_k   = (const float*)d_in[8];
    const float* maa_v   = (const float*)d_in[9];
    const float* maa_r   = (const float*)d_in[10];
    const float* maa_g   = (const float*)d_in[11];
    const float* maa_w1  = (const float*)d_in[12];  // [E, 320]
    const float* maa_w2  = (const float*)d_in[13];  // [5, 64, E]
    const float* faaaa   = (const float*)d_in[17];  // [H, 64]
    const float* Wr      = (const float*)d_in[18];
    const float* Wk      = (const float*)d_in[19];
    const float* Wv      = (const float*)d_in[20];
    const float* Wo      = (const float*)d_in[21];
    const float* Wg      = (const float*)d_in[22];
    const float* gn_w    = (const float*)d_in[23];
    const float* gn_b    = (const float*)d_in[24];
    const float* f_maa_k = (const float*)d_in[25];
    const float* f_maa_r = (const float*)d_in[26];
    const float* ffn_Wk  = (const float*)d_in[27];
    const float* ffn_Wr  = (const float*)d_in[28];
    const float* ffn_Wv  = (const float*)d_in[29];
    float* out = (float*)d_out;

    cudaFuncSetAttribute(gemm_k<EPI_TANH,   false>, cudaFuncAttributeMaxDynamicSharedMemorySize, (int)SMEM_BYTES);
    cudaFuncSetAttribute(gemm_k<EPI_MIX,    false>, cudaFuncAttributeMaxDynamicSharedMemorySize, (int)SMEM_BYTES);
    cudaFuncSetAttribute(gemm_k<EPI_NONE,   true >, cudaFuncAttributeMaxDynamicSharedMemorySize, (int)SMEM_BYTES);
    cudaFuncSetAttribute(gemm_k<EPI_SILU,   true >, cudaFuncAttributeMaxDynamicSharedMemorySize, (int)SMEM_BYTES);
    cudaFuncSetAttribute(gemm_k<EPI_ADDC,   true >, cudaFuncAttributeMaxDynamicSharedMemorySize, (int)SMEM_BYTES);
    cudaFuncSetAttribute(gemm_k<EPI_SIGMOID,true >, cudaFuncAttributeMaxDynamicSharedMemorySize, (int)SMEM_BYTES);
    cudaFuncSetAttribute(gemm_k<EPI_RELUSQ, true >, cudaFuncAttributeMaxDynamicSharedMemorySize, (int)SMEM_BYTES);
    cudaFuncSetAttribute(gemm_k<EPI_FFNOUT, true >, cudaFuncAttributeMaxDynamicSharedMemorySize, (int)SMEM_BYTES);

    float* scr = nullptr;
    cudaGetSymbolAddress((void**)&scr, g_scr);
    auto S = [&](int i) { return scr + (size_t)i * BATCH * EMB; };
    float *xn = S(SL_XN), *sx = S(SL_SX), *xmix = S(SL_XMIX);
    float *xk = S(SL_XK), *xv = S(SL_XV), *xrb = S(SL_XR), *xg = S(SL_XG);
    float *rb = S(SL_R), *kb = S(SL_K), *vb = S(SL_V), *gb = S(SL_G);
    float *zb = S(SL_Z), *x1 = S(SL_X1);
    float *xk2 = S(SL_XK2), *xr2 = S(SL_XR2);
    float *rr = S(SL_RR), *kk = S(SL_KK), *tb = S(SL_T);

    dim3 blk(256);
    dim3 gE(EMB / BN, BATCH / BM);      // 32 x 8
    dim3 gT(320 / BN, BATCH / BM);      // 5 x 8

    ln_mix1<<<BATCH, blk>>>(x, state, ln1_w, ln1_b, maa_x, xn, sx, xmix);

    gemm_k<EPI_TANH, false><<<gT, blk, SMEM_BYTES>>>(xmix, EMB, maa_w1, 320, tb, 320,
                                         BATCH, 320, EMB, nullptr, nullptr, nullptr);

    gemm_k<EPI_MIX, false><<<gE, blk, SMEM_BYTES>>>(tb + 64*1, 320, maa_w2 + (size_t)1*64*EMB, EMB,
                                        xk, EMB, BATCH, EMB, 64, xn, sx, maa_k);
    gemm_k<EPI_MIX, false><<<gE, blk, SMEM_BYTES>>>(tb + 64*2, 320, maa_w2 + (size_t)2*64*EMB, EMB,
                                        xv, EMB, BATCH, EMB, 64, xn, sx, maa_v);
    gemm_k<EPI_MIX, false><<<gE, blk, SMEM_BYTES>>>(tb + 64*3, 320, maa_w2 + (size_t)3*64*EMB, EMB,
                                        xrb, EMB, BATCH, EMB, 64, xn, sx, maa_r);
    gemm_k<EPI_MIX, false><<<gE, blk, SMEM_BYTES>>>(tb + 64*4, 320, maa_w2 + (size_t)4*64*EMB, EMB,
                                        xg, EMB, BATCH, EMB, 64, xn, sx, maa_g);

    gemm_k<EPI_NONE, true><<<gE, blk, SMEM_BYTES>>>(xrb, EMB, Wr, EMB, rb, EMB,
                                        BATCH, EMB, EMB, nullptr, nullptr, nullptr);
    gemm_k<EPI_NONE, true><<<gE, blk, SMEM_BYTES>>>(xk, EMB, Wk, EMB, kb, EMB,
                                        BATCH, EMB, EMB, nullptr, nullptr, nullptr);
    gemm_k<EPI_NONE, true><<<gE, blk, SMEM_BYTES>>>(xv, EMB, Wv, EMB, vb, EMB,
                                        BATCH, EMB, EMB, nullptr, nullptr, nullptr);
    gemm_k<EPI_SILU, true><<<gE, blk, SMEM_BYTES>>>(xg, EMB, Wg, EMB, gb, EMB,
                                        BATCH, EMB, EMB, nullptr, nullptr, nullptr);

    wkv_gn<<<BATCH * NHEAD, 64>>>(rb, kb, vb, gb, state, faaaa, gn_w, gn_b, zb);

    gemm_k<EPI_ADDC, true><<<gE, blk, SMEM_BYTES>>>(zb, EMB, Wo, EMB, x1, EMB,
                                        BATCH, EMB, EMB, x, nullptr, nullptr);

    ln_mix2<<<BATCH, blk>>>(x1, state, ln2_w, ln2_b, f_maa_k, f_maa_r, xk2, xr2);
    gemm_k<EPI_SIGMOID, true><<<gE, blk, SMEM_BYTES>>>(xr2, EMB, ffn_Wr, EMB, rr, EMB,
                                           BATCH, EMB, EMB, nullptr, nullptr, nullptr);
    gemm_k<EPI_RELUSQ, true><<<gE, blk, SMEM_BYTES>>>(xk2, EMB, ffn_Wk, EMB, kk, EMB,
                                          BATCH, EMB, EMB, nullptr, nullptr, nullptr);
    gemm_k<EPI_FFNOUT, true><<<gE, blk, SMEM_BYTES>>>(kk, EMB, ffn_Wv, EMB, out, EMB,
                                          BATCH, EMB, EMB, x1, rr, nullptr);
}

// round 7
// speedup vs baseline: 1.1805x; 1.0353x over previous
#include <cuda_runtime.h>
#include <mma.h>
using namespace nvcuda;

#define BATCH 1024
#define EMB   2048
#define NHEAD 32
#define HSZ   64
#define SROWS 66

// ---------------- scratch (no allocations allowed) ----------------
__device__ float g_scr[(size_t)18 * BATCH * EMB];

#define SL_XN   0
#define SL_SX   1
#define SL_XMIX 2
#define SL_XK   3
#define SL_XV   4
#define SL_XR   5
#define SL_XG   6
#define SL_R    7
#define SL_K    8
#define SL_V    9
#define SL_G    10
#define SL_Z    11
#define SL_X1   12
#define SL_XK2  13
#define SL_XR2  14
#define SL_RR   15
#define SL_KK   16
#define SL_T    17

#define EPI_NONE    0
#define EPI_TANH    1
#define EPI_SILU    2
#define EPI_SIGMOID 3
#define EPI_RELUSQ  4
#define EPI_ADDC    5   // out = acc + aux1
#define EPI_MIX     6   // out = aux1 + aux2*(vec1[n] + acc)
#define EPI_FFNOUT  7   // out = aux1 + aux2*acc

// ---------------- 3xTF32 wmma GEMM, double-buffered pipeline ----------------
// C[M,N] = A[M,K] @ op(B); C ≈ Ah*Bh + Ah*Bl + Al*Bh (fp32-accurate)
constexpr int BM = 128, BN = 64, BK = 32;
constexpr int LDA_S  = BK + 4;  // 36
constexpr int LDBT_S = BK + 4;  // 36 ([BN][36])
constexpr int LDBN_S = BN + 4;  // 68 ([BK][68])
constexpr int LDC_S  = BN + 4;  // 68
constexpr int ASZ = BM * LDA_S;             // 4608
constexpr int BSZ = BN * LDBT_S;            // 2304 (>= BK*LDBN_S=2176)
constexpr int STAGE_FLOATS = 2 * ASZ + 2 * BSZ;      // 13824
constexpr int SMEM_FLOATS  = 2 * STAGE_FLOATS;       // 27648
constexpr size_t SMEM_BYTES = SMEM_FLOATS * sizeof(float);  // 110592

__device__ __forceinline__ void split_tf32(float v, float& h, float& l) {
    h = wmma::__float_to_tf32(v);
    l = wmma::__float_to_tf32(v - h);
}

template<int EPI, bool BT>
__global__ void __launch_bounds__(256, 2)
gemm_k(const float* __restrict__ A, int lda,
       const float* __restrict__ Bw, int ldb,
       float* __restrict__ C, int ldc,
       int M, int N, int K,
       const float* __restrict__ aux1,
       const float* __restrict__ aux2,
       const float* __restrict__ vec1)
{
    extern __shared__ float smem[];

    const int tid  = threadIdx.x;
    const int m0   = blockIdx.y * BM;
    const int n0   = blockIdx.x * BN;
    const int w    = tid >> 5;
    const int wm   = (w >> 1) * 32;
    const int wn   = (w & 1) * 32;

    // register staging for global->smem pipeline
    float rA[16];
    float rB[8];

    auto load_tiles = [&](int k0) {
        #pragma unroll
        for (int it = 0; it < 4; it++) {
            int idx = tid + it * 256;
            int m   = idx >> 3;
            int kq  = (idx & 7) << 2;
            float4 a4 = *reinterpret_cast<const float4*>(
                &A[(size_t)(m0 + m) * lda + k0 + kq]);
            rA[it*4+0] = a4.x; rA[it*4+1] = a4.y;
            rA[it*4+2] = a4.z; rA[it*4+3] = a4.w;
        }
        if (BT) {
            #pragma unroll
            for (int it = 0; it < 2; it++) {
                int idx = tid + it * 256;
                int n   = idx >> 3;
                int kq  = (idx & 7) << 2;
                float4 b4 = *reinterpret_cast<const float4*>(
                    &Bw[(size_t)(n0 + n) * ldb + k0 + kq]);
                rB[it*4+0] = b4.x; rB[it*4+1] = b4.y;
                rB[it*4+2] = b4.z; rB[it*4+3] = b4.w;
            }
        } else {
            #pragma unroll
            for (int it = 0; it < 2; it++) {
                int idx = tid + it * 256;
                int k   = idx >> 4;
                int nq  = (idx & 15) << 2;
                float4 b4 = *reinterpret_cast<const float4*>(
                    &Bw[(size_t)(k0 + k) * ldb + n0 + nq]);
                rB[it*4+0] = b4.x; rB[it*4+1] = b4.y;
                rB[it*4+2] = b4.z; rB[it*4+3] = b4.w;
            }
        }
    };

    auto store_tiles = [&](int stage) {
        float* Ah = smem + stage * STAGE_FLOATS;
        float* Al = Ah + ASZ;
        float* Bh = Al + ASZ;
        float* Bl = Bh + BSZ;
        #pragma unroll
        for (int it = 0; it < 4; it++) {
            int idx = tid + it * 256;
            int m   = idx >> 3;
            int kq  = (idx & 7) << 2;
            #pragma unroll
            for (int q = 0; q < 4; q++) {
                float h, l; split_tf32(rA[it*4+q], h, l);
                Ah[m*LDA_S+kq+q] = h; Al[m*LDA_S+kq+q] = l;
            }
        }
        if (BT) {
            #pragma unroll
            for (int it = 0; it < 2; it++) {
                int idx = tid + it * 256;
                int n   = idx >> 3;
                int kq  = (idx & 7) << 2;
                #pragma unroll
                for (int q = 0; q < 4; q++) {
                    float h, l; split_tf32(rB[it*4+q], h, l);
                    Bh[n*LDBT_S+kq+q] = h; Bl[n*LDBT_S+kq+q] = l;
                }
            }
        } else {
            #pragma unroll
            for (int it = 0; it < 2; it++) {
                int idx = tid + it * 256;
                int k   = idx >> 4;
                int nq  = (idx & 15) << 2;
                #pragma unroll
                for (int q = 0; q < 4; q++) {
                    float h, l; split_tf32(rB[it*4+q], h, l);
                    Bh[k*LDBN_S+nq+q] = h; Bl[k*LDBN_S+nq+q] = l;
                }
            }
        }
    };

    wmma::fragment<wmma::accumulator, 16, 16, 8, float> fc[2][2];
    #pragma unroll
    for (int i = 0; i < 2; i++)
        #pragma unroll
        for (int j = 0; j < 2; j++)
            wmma::fill_fragment(fc[i][j], 0.0f);

    auto mma_stage = [&](int stage) {
        float* Ah = smem + stage * STAGE_FLOATS;
        float* Al = Ah + ASZ;
        float* Bh = Al + ASZ;
        float* Bl = Bh + BSZ;
        #pragma unroll
        for (int kk8 = 0; kk8 < BK; kk8 += 8) {
            wmma::fragment<wmma::matrix_a, 16, 16, 8, wmma::precision::tf32,
                           wmma::row_major> fah[2], fal[2];
            #pragma unroll
            for (int i = 0; i < 2; i++) {
                wmma::load_matrix_sync(fah[i], &Ah[(wm + i*16) * LDA_S + kk8], LDA_S);
                wmma::load_matrix_sync(fal[i], &Al[(wm + i*16) * LDA_S + kk8], LDA_S);
            }
            if (BT) {
                wmma::fragment<wmma::matrix_b, 16, 16, 8, wmma::precision::tf32,
                               wmma::col_major> fbh[2], fbl[2];
                #pragma unroll
                for (int j = 0; j < 2; j++) {
                    wmma::load_matrix_sync(fbh[j], &Bh[(wn + j*16) * LDBT_S + kk8], LDBT_S);
                    wmma::load_matrix_sync(fbl[j], &Bl[(wn + j*16) * LDBT_S + kk8], LDBT_S);
                }
                #pragma unroll
                for (int i = 0; i < 2; i++)
                    #pragma unroll
                    for (int j = 0; j < 2; j++) {
                        wmma::mma_sync(fc[i][j], fal[i], fbh[j], fc[i][j]);
                        wmma::mma_sync(fc[i][j], fah[i], fbl[j], fc[i][j]);
                        wmma::mma_sync(fc[i][j], fah[i], fbh[j], fc[i][j]);
                    }
            } else {
                wmma::fragment<wmma::matrix_b, 16, 16, 8, wmma::precision::tf32,
                               wmma::row_major> fbh[2], fbl[2];
                #pragma unroll
                for (int j = 0; j < 2; j++) {
                    wmma::load_matrix_sync(fbh[j], &Bh[kk8 * LDBN_S + wn + j*16], LDBN_S);
                    wmma::load_matrix_sync(fbl[j], &Bl[kk8 * LDBN_S + wn + j*16], LDBN_S);
                }
                #pragma unroll
                for (int i = 0; i < 2; i++)
                    #pragma unroll
                    for (int j = 0; j < 2; j++) {
                        wmma::mma_sync(fc[i][j], fal[i], fbh[j], fc[i][j]);
                        wmma::mma_sync(fc[i][j], fah[i], fbl[j], fc[i][j]);
                        wmma::mma_sync(fc[i][j], fah[i], fbh[j], fc[i][j]);
                    }
            }
        }
    };

    const int nIter = K / BK;

    // prologue: tile 0 into stage 0
    load_tiles(0);
    store_tiles(0);
    __syncthreads();

    for (int it = 0; it < nIter; it++) {
        int cur = it & 1;
        bool more = (it + 1 < nIter);
        if (more) load_tiles((it + 1) * BK);   // LDG overlapped with MMAs below
        mma_stage(cur);
        if (more) {
            store_tiles(cur ^ 1);              // waits on LDG; writes the other buffer
            __syncthreads();                   // one barrier per iteration
        }
    }
    __syncthreads();   // all MMAs done before smem reuse for C tile

    // C tile via smem (reuse)
    #pragma unroll
    for (int i = 0; i < 2; i++)
        #pragma unroll
        for (int j = 0; j < 2; j++)
            wmma::store_matrix_sync(&smem[(wm + i*16) * LDC_S + wn + j*16],
                                    fc[i][j], LDC_S, wmma::mem_row_major);
    __syncthreads();

    #pragma unroll
    for (int it = 0; it < 32; it++) {
        int idx = tid + it * 256;
        int m   = idx >> 6;
        int n   = idx & 63;
        float acc = smem[m * LDC_S + n];
        size_t gi = (size_t)(m0 + m) * ldc + n0 + n;
        float o;
        if (EPI == EPI_NONE)        o = acc;
        else if (EPI == EPI_TANH)   o = tanhf(acc);
        else if (EPI == EPI_SILU)   o = acc / (1.0f + __expf(-acc));
        else if (EPI == EPI_SIGMOID) o = 1.0f / (1.0f + __expf(-acc));
        else if (EPI == EPI_RELUSQ) { float rv = fmaxf(acc, 0.0f); o = rv * rv; }
        else if (EPI == EPI_ADDC)   o = acc + aux1[gi];
        else if (EPI == EPI_MIX)    o = aux1[gi] + aux2[gi] * (vec1[n0 + n] + acc);
        else /* EPI_FFNOUT */       o = aux1[gi] + aux2[gi] * acc;
        C[gi] = o;
    }
}

// ---------------- ln + token-shift fuse (time mix) ----------------
__global__ void __launch_bounds__(256)
ln_mix1(const float* __restrict__ x, const float* __restrict__ state,
        const float* __restrict__ lnw, const float* __restrict__ lnb,
        const float* __restrict__ maa_x,
        float* __restrict__ xn_o, float* __restrict__ sx_o,
        float* __restrict__ xmix_o)
{
    int b = blockIdx.x;
    const float* xr = x + (size_t)b * EMB;
    float v[8]; float s = 0.f, sq = 0.f;
    #pragma unroll
    for (int i = 0; i < 8; i++) {
        v[i] = xr[threadIdx.x + i * 256];
        s += v[i]; sq += v[i] * v[i];
    }
    __shared__ float red[16];
    #pragma unroll
    for (int o = 16; o > 0; o >>= 1) {
        s  += __shfl_down_sync(0xffffffffu, s,  o);
        sq += __shfl_down_sync(0xffffffffu, sq, o);
    }
    int w = threadIdx.x >> 5;
    if ((threadIdx.x & 31) == 0) { red[w] = s; red[w + 8] = sq; }
    __syncthreads();
    if (threadIdx.x == 0) {
        float ts = 0.f, tq = 0.f;
        for (int i = 0; i < 8; i++) { ts += red[i]; tq += red[i + 8]; }
        red[0] = ts; red[8] = tq;
    }
    __syncthreads();
    float mu  = red[0] * (1.0f / EMB);
    float var = red[8] * (1.0f / EMB) - mu * mu;
    float rs  = rsqrtf(var + 1e-5f);
    const float* srow = state + ((size_t)b * SROWS + 1) * EMB;
    #pragma unroll
    for (int i = 0; i < 8; i++) {
        int e = threadIdx.x + i * 256;
        float xnv = (v[i] - mu) * rs * lnw[e] + lnb[e];
        float sxv = srow[e] - xnv;
        size_t gi = (size_t)b * EMB + e;
        xn_o[gi] = xnv;
        sx_o[gi] = sxv;
        xmix_o[gi] = xnv + sxv * maa_x[e];
    }
}

// ---------------- ln + token-shift fuse (channel mix) ----------------
__global__ void __launch_bounds__(256)
ln_mix2(const float* __restrict__ x1, const float* __restrict__ state,
        const float* __restrict__ lnw, const float* __restrict__ lnb,
        const float* __restrict__ maa_k, const float* __restrict__ maa_r,
        float* __restrict__ xk_o, float* __restrict__ xr_o)
{
    int b = blockIdx.x;
    const float* xr = x1 + (size_t)b * EMB;
    float v[8]; float s = 0.f, sq = 0.f;
    #pragma unroll
    for (int i = 0; i < 8; i++) {
        v[i] = xr[threadIdx.x + i * 256];
        s += v[i]; sq += v[i] * v[i];
    }
    __shared__ float red[16];
    #pragma unroll
    for (int o = 16; o > 0; o >>= 1) {
        s  += __shfl_down_sync(0xffffffffu, s,  o);
        sq += __shfl_down_sync(0xffffffffu, sq, o);
    }
    int w = threadIdx.x >> 5;
    if ((threadIdx.x & 31) == 0) { red[w] = s; red[w + 8] = sq; }
    __syncthreads();
    if (threadIdx.x == 0) {
        float ts = 0.f, tq = 0.f;
        for (int i = 0; i < 8; i++) { ts += red[i]; tq += red[i + 8]; }
        red[0] = ts; red[8] = tq;
    }
    __syncthreads();
    float mu  = red[0] * (1.0f / EMB);
    float var = red[8] * (1.0f / EMB) - mu * mu;
    float rs  = rsqrtf(var + 1e-5f);
    const float* srow = state + (size_t)b * SROWS * EMB;  // row 0
    #pragma unroll
    for (int i = 0; i < 8; i++) {
        int e = threadIdx.x + i * 256;
        float xnv = (v[i] - mu) * rs * lnw[e] + lnb[e];
        float sxv = srow[e] - xnv;
        size_t gi = (size_t)b * EMB + e;
        xk_o[gi] = xnv + sxv * maa_k[e];
        xr_o[gi] = xnv + sxv * maa_r[e];
    }
}

// ---------------- wkv readout + groupnorm + (pre-silu'ed) gate ----------------
__global__ void __launch_bounds__(64)
wkv_gn(const float* __restrict__ r, const float* __restrict__ k,
       const float* __restrict__ v, const float* __restrict__ gp,
       const float* __restrict__ state, const float* __restrict__ faaaa,
       const float* __restrict__ gnw, const float* __restrict__ gnb,
       float* __restrict__ z)
{
    int bh = blockIdx.x;
    int b  = bh >> 5;
    int h  = bh & 31;
    int j  = threadIdx.x;  // 0..63
    size_t off = (size_t)b * EMB + h * 64 + j;
    float rv = r[off], kv = k[off], vv = v[off];
    float fv = faaaa[h * 64 + j];

    __shared__ float rs_sh[64];
    __shared__ float red1[2];
    __shared__ float red2[4];
    rs_sh[j] = rv;

    float p = rv * fv * kv;
    #pragma unroll
    for (int o = 16; o > 0; o >>= 1) p += __shfl_down_sync(0xffffffffu, p, o);
    int w = j >> 5;
    if ((j & 31) == 0) red1[w] = p;
    __syncthreads();
    float coef = red1[0] + red1[1];

    const float* sb = state + ((size_t)b * SROWS + 2 + 2 * h) * EMB;
    float acc = 0.f;
    #pragma unroll
    for (int i = 0; i < 64; i++)
        acc += rs_sh[i] * sb[(i >> 5) * EMB + ((i & 31) << 6) + j];

    float y = coef * vv + acc;

    float s = y, sq = y * y;
    #pragma unroll
    for (int o = 16; o > 0; o >>= 1) {
        s  += __shfl_down_sync(0xffffffffu, s,  o);
        sq += __shfl_down_sync(0xffffffffu, sq, o);
    }
    if ((j & 31) == 0) { red2[w] = s; red2[2 + w] = sq; }
    __syncthreads();
    float mu  = (red2[0] + red2[1]) * (1.0f / 64.0f);
    float var = (red2[2] + red2[3]) * (1.0f / 64.0f) - mu * mu;
    float zn  = (y - mu) * rsqrtf(var + 1e-5f) * gnw[h * 64 + j] + gnb[h * 64 + j];
    // gp is ALREADY silu(xg@Wg.T) — do NOT re-apply silu.
    z[off] = zn * gp[off];
}

// ---------------- launch ----------------
extern "C" void kernel_launch(void* const* d_in, const int* in_sizes, int n_in,
                              void* d_out, int out_size)
{
    (void)in_sizes; (void)n_in; (void)out_size;
    const float* x       = (const float*)d_in[0];
    const float* state   = (const float*)d_in[1];
    const float* ln1_w   = (const float*)d_in[2];
    const float* ln1_b   = (const float*)d_in[3];
    const float* ln2_w   = (const float*)d_in[4];
    const float* ln2_b   = (const float*)d_in[5];
    const float* maa_x   = (const float*)d_in[6];
    const float* maa_k   = (const float*)d_in[8];
    const float* maa_v   = (const float*)d_in[9];
    const float* maa_r   = (const float*)d_in[10];
    const float* maa_g   = (const float*)d_in[11];
    const float* maa_w1  = (const float*)d_in[12];  // [E, 320]
    const float* maa_w2  = (const float*)d_in[13];  // [5, 64, E]
    const float* faaaa   = (const float*)d_in[17];  // [H, 64]
    const float* Wr      = (const float*)d_in[18];
    const float* Wk      = (const float*)d_in[19];
    const float* Wv      = (const float*)d_in[20];
    const float* Wo      = (const float*)d_in[21];
    const float* Wg      = (const float*)d_in[22];
    const float* gn_w    = (const float*)d_in[23];
    const float* gn_b    = (const float*)d_in[24];
    const float* f_maa_k = (const float*)d_in[25];
    const float* f_maa_r = (const float*)d_in[26];
    const float* ffn_Wk  = (const float*)d_in[27];
    const float* ffn_Wr  = (const float*)d_in[28];
    const float* ffn_Wv  = (const float*)d_in[29];
    float* out = (float*)d_out;

    cudaFuncSetAttribute(gemm_k<EPI_TANH,   false>, cudaFuncAttributeMaxDynamicSharedMemorySize, (int)SMEM_BYTES);
    cudaFuncSetAttribute(gemm_k<EPI_MIX,    false>, cudaFuncAttributeMaxDynamicSharedMemorySize, (int)SMEM_BYTES);
    cudaFuncSetAttribute(gemm_k<EPI_NONE,   true >, cudaFuncAttributeMaxDynamicSharedMemorySize, (int)SMEM_BYTES);
    cudaFuncSetAttribute(gemm_k<EPI_SILU,   true >, cudaFuncAttributeMaxDynamicSharedMemorySize, (int)SMEM_BYTES);
    cudaFuncSetAttribute(gemm_k<EPI_ADDC,   true >, cudaFuncAttributeMaxDynamicSharedMemorySize, (int)SMEM_BYTES);
    cudaFuncSetAttribute(gemm_k<EPI_SIGMOID,true >, cudaFuncAttributeMaxDynamicSharedMemorySize, (int)SMEM_BYTES);
    cudaFuncSetAttribute(gemm_k<EPI_RELUSQ, true >, cudaFuncAttributeMaxDynamicSharedMemorySize, (int)SMEM_BYTES);
    cudaFuncSetAttribute(gemm_k<EPI_FFNOUT, true >, cudaFuncAttributeMaxDynamicSharedMemorySize, (int)SMEM_BYTES);

    float* scr = nullptr;
    cudaGetSymbolAddress((void**)&scr, g_scr);
    auto S = [&](int i) { return scr + (size_t)i * BATCH * EMB; };
    float *xn = S(SL_XN), *sx = S(SL_SX), *xmix = S(SL_XMIX);
    float *xk = S(SL_XK), *xv = S(SL_XV), *xrb = S(SL_XR), *xg = S(SL_XG);
    float *rb = S(SL_R), *kb = S(SL_K), *vb = S(SL_V), *gb = S(SL_G);
    float *zb = S(SL_Z), *x1 = S(SL_X1);
    float *xk2 = S(SL_XK2), *xr2 = S(SL_XR2);
    float *rr = S(SL_RR), *kk = S(SL_KK), *tb = S(SL_T);

    dim3 blk(256);
    dim3 gE(EMB / BN, BATCH / BM);      // 32 x 8
    dim3 gT(320 / BN, BATCH / BM);      // 5 x 8

    ln_mix1<<<BATCH, blk>>>(x, state, ln1_w, ln1_b, maa_x, xn, sx, xmix);

    gemm_k<EPI_TANH, false><<<gT, blk, SMEM_BYTES>>>(xmix, EMB, maa_w1, 320, tb, 320,
                                         BATCH, 320, EMB, nullptr, nullptr, nullptr);

    gemm_k<EPI_MIX, false><<<gE, blk, SMEM_BYTES>>>(tb + 64*1, 320, maa_w2 + (size_t)1*64*EMB, EMB,
                                        xk, EMB, BATCH, EMB, 64, xn, sx, maa_k);
    gemm_k<EPI_MIX, false><<<gE, blk, SMEM_BYTES>>>(tb + 64*2, 320, maa_w2 + (size_t)2*64*EMB, EMB,
                                        xv, EMB, BATCH, EMB, 64, xn, sx, maa_v);
    gemm_k<EPI_MIX, false><<<gE, blk, SMEM_BYTES>>>(tb + 64*3, 320, maa_w2 + (size_t)3*64*EMB, EMB,
                                        xrb, EMB, BATCH, EMB, 64, xn, sx, maa_r);
    gemm_k<EPI_MIX, false><<<gE, blk, SMEM_BYTES>>>(tb + 64*4, 320, maa_w2 + (size_t)4*64*EMB, EMB,
                                        xg, EMB, BATCH, EMB, 64, xn, sx, maa_g);

    gemm_k<EPI_NONE, true><<<gE, blk, SMEM_BYTES>>>(xrb, EMB, Wr, EMB, rb, EMB,
                                        BATCH, EMB, EMB, nullptr, nullptr, nullptr);
    gemm_k<EPI_NONE, true><<<gE, blk, SMEM_BYTES>>>(xk, EMB, Wk, EMB, kb, EMB,
                                        BATCH, EMB, EMB, nullptr, nullptr, nullptr);
    gemm_k<EPI_NONE, true><<<gE, blk, SMEM_BYTES>>>(xv, EMB, Wv, EMB, vb, EMB,
                                        BATCH, EMB, EMB, nullptr, nullptr, nullptr);
    gemm_k<EPI_SILU, true><<<gE, blk, SMEM_BYTES>>>(xg, EMB, Wg, EMB, gb, EMB,
                                        BATCH, EMB, EMB, nullptr, nullptr, nullptr);

    wkv_gn<<<BATCH * NHEAD, 64>>>(rb, kb, vb, gb, state, faaaa, gn_w, gn_b, zb);

    gemm_k<EPI_ADDC, true><<<gE, blk, SMEM_BYTES>>>(zb, EMB, Wo, EMB, x1, EMB,
                                        BATCH, EMB, EMB, x, nullptr, nullptr);

    ln_mix2<<<BATCH, blk>>>(x1, state, ln2_w, ln2_b, f_maa_k, f_maa_r, xk2, xr2);
    gemm_k<EPI_SIGMOID, true><<<gE, blk, SMEM_BYTES>>>(xr2, EMB, ffn_Wr, EMB, rr, EMB,
                                           BATCH, EMB, EMB, nullptr, nullptr, nullptr);
    gemm_k<EPI_RELUSQ, true><<<gE, blk, SMEM_BYTES>>>(xk2, EMB, ffn_Wk, EMB, kk, EMB,
                                          BATCH, EMB, EMB, nullptr, nullptr, nullptr);
    gemm_k<EPI_FFNOUT, true><<<gE, blk, SMEM_BYTES>>>(kk, EMB, ffn_Wv, EMB, out, EMB,
                                          BATCH, EMB, EMB, x1, rr, nullptr);
}

// round 13
// speedup vs baseline: 1.3257x; 1.1230x over previous
#include <cuda_runtime.h>
#include <cuda_pipeline.h>
#include <mma.h>
using namespace nvcuda;

#define BATCH 1024
#define EMB   2048
#define NHEAD 32
#define HSZ   64
#define SROWS 66

// ---------------- scratch (no allocations allowed) ----------------
__device__ float g_scr[(size_t)18 * BATCH * EMB];

#define SL_XN   0
#define SL_SX   1
#define SL_XMIX 2
#define SL_XK   3
#define SL_XV   4
#define SL_XR   5
#define SL_XG   6
#define SL_R    7
#define SL_K    8
#define SL_V    9
#define SL_G    10
#define SL_Z    11
#define SL_X1   12
#define SL_XK2  13
#define SL_XR2  14
#define SL_RR   15
#define SL_KK   16
#define SL_T    17

#define EPI_NONE    0
#define EPI_TANH    1
#define EPI_SILU    2
#define EPI_SIGMOID 3
#define EPI_RELUSQ  4
#define EPI_ADDC    5   // out = acc + aux1
#define EPI_MIX     6   // out = aux1 + aux2*(vec1[n] + acc)
#define EPI_FFNOUT  7   // out = aux1 + aux2*acc

// ---------------- 3xTF32 wmma GEMM, cp.async 3-stage pipeline ----------------
// C[M,N] = A[M,K] @ op(B); C ≈ Ah*Bh + Ah*Bl + Al*Bh (fp32-accurate).
// smem holds RAW fp32 tiles (cp.async); hi/lo tf32 split happens on fragment
// registers — bit-identical math to previous rounds.
constexpr int BM = 128, BN = 64, BK = 32;
constexpr int LDA_S  = BK + 4;  // 36
constexpr int LDBT_S = BK + 4;  // 36 ([BN][36])
constexpr int LDBN_S = BN + 4;  // 68 ([BK][68])
constexpr int LDC_S  = BN + 4;  // 68
constexpr int ASZ = BM * LDA_S;                 // 4608
constexpr int BSZ = BN * LDBT_S;                // 2304 (>= BK*LDBN_S=2176)
constexpr int STAGE_FLOATS = ASZ + BSZ;         // 6912
constexpr int NSTAGE = 3;
constexpr int SMEM_FLOATS  = NSTAGE * STAGE_FLOATS;        // 20736
constexpr size_t SMEM_BYTES = SMEM_FLOATS * sizeof(float); // 82944

template<int EPI, bool BT>
__global__ void __launch_bounds__(256, 2)
gemm_k(const float* __restrict__ A, int lda,
       const float* __restrict__ Bw, int ldb,
       float* __restrict__ C, int ldc,
       int M, int N, int K,
       const float* __restrict__ aux1,
       const float* __restrict__ aux2,
       const float* __restrict__ vec1)
{
    extern __shared__ float smem[];

    const int tid  = threadIdx.x;
    const int m0   = blockIdx.y * BM;
    const int n0   = blockIdx.x * BN;
    const int w    = tid >> 5;
    const int wm   = (w >> 1) * 32;
    const int wn   = (w & 1) * 32;

    // async global->smem copy of one K-tile into stage s (raw fp32)
    auto issue_cp = [&](int stage, int k0) {
        float* As = smem + stage * STAGE_FLOATS;
        float* Bs = As + ASZ;
        #pragma unroll
        for (int it = 0; it < 4; it++) {
            int idx = tid + it * 256;
            int m   = idx >> 3;
            int kq  = (idx & 7) << 2;
            __pipeline_memcpy_async(&As[m * LDA_S + kq],
                                    &A[(size_t)(m0 + m) * lda + k0 + kq], 16);
        }
        if (BT) {
            #pragma unroll
            for (int it = 0; it < 2; it++) {
                int idx = tid + it * 256;
                int n   = idx >> 3;
                int kq  = (idx & 7) << 2;
                __pipeline_memcpy_async(&Bs[n * LDBT_S + kq],
                                        &Bw[(size_t)(n0 + n) * ldb + k0 + kq], 16);
            }
        } else {
            #pragma unroll
            for (int it = 0; it < 2; it++) {
                int idx = tid + it * 256;
                int k   = idx >> 4;
                int nq  = (idx & 15) << 2;
                __pipeline_memcpy_async(&Bs[k * LDBN_S + nq],
                                        &Bw[(size_t)(k0 + k) * ldb + n0 + nq], 16);
            }
        }
    };

    wmma::fragment<wmma::accumulator, 16, 16, 8, float> fc[2][2];
    #pragma unroll
    for (int i = 0; i < 2; i++)
        #pragma unroll
        for (int j = 0; j < 2; j++)
            wmma::fill_fragment(fc[i][j], 0.0f);

    auto mma_stage = [&](int stage) {
        float* As = smem + stage * STAGE_FLOATS;
        float* Bs = As + ASZ;
        #pragma unroll
        for (int kk8 = 0; kk8 < BK; kk8 += 8) {
            wmma::fragment<wmma::matrix_a, 16, 16, 8, wmma::precision::tf32,
                           wmma::row_major> fah[2], fal[2];
            #pragma unroll
            for (int i = 0; i < 2; i++) {
                wmma::load_matrix_sync(fah[i], &As[(wm + i*16) * LDA_S + kk8], LDA_S);
                #pragma unroll
                for (int e = 0; e < fah[i].num_elements; e++) {
                    float v = fah[i].x[e];
                    float h = wmma::__float_to_tf32(v);
                    fah[i].x[e] = h;
                    fal[i].x[e] = wmma::__float_to_tf32(v - h);
                }
            }
            if (BT) {
                wmma::fragment<wmma::matrix_b, 16, 16, 8, wmma::precision::tf32,
                               wmma::col_major> fbh[2], fbl[2];
                #pragma unroll
                for (int j = 0; j < 2; j++) {
                    wmma::load_matrix_sync(fbh[j], &Bs[(wn + j*16) * LDBT_S + kk8], LDBT_S);
                    #pragma unroll
                    for (int e = 0; e < fbh[j].num_elements; e++) {
                        float v = fbh[j].x[e];
                        float h = wmma::__float_to_tf32(v);
                        fbh[j].x[e] = h;
                        fbl[j].x[e] = wmma::__float_to_tf32(v - h);
                    }
                }
                #pragma unroll
                for (int i = 0; i < 2; i++)
                    #pragma unroll
                    for (int j = 0; j < 2; j++) {
                        wmma::mma_sync(fc[i][j], fal[i], fbh[j], fc[i][j]);
                        wmma::mma_sync(fc[i][j], fah[i], fbl[j], fc[i][j]);
                        wmma::mma_sync(fc[i][j], fah[i], fbh[j], fc[i][j]);
                    }
            } else {
                wmma::fragment<wmma::matrix_b, 16, 16, 8, wmma::precision::tf32,
                               wmma::row_major> fbh[2], fbl[2];
                #pragma unroll
                for (int j = 0; j < 2; j++) {
                    wmma::load_matrix_sync(fbh[j], &Bs[kk8 * LDBN_S + wn + j*16], LDBN_S);
                    #pragma unroll
                    for (int e = 0; e < fbh[j].num_elements; e++) {
                        float v = fbh[j].x[e];
                        float h = wmma::__float_to_tf32(v);
                        fbh[j].x[e] = h;
                        fbl[j].x[e] = wmma::__float_to_tf32(v - h);
                    }
                }
                #pragma unroll
                for (int i = 0; i < 2; i++)
                    #pragma unroll
                    for (int j = 0; j < 2; j++) {
                        wmma::mma_sync(fc[i][j], fal[i], fbh[j], fc[i][j]);
                        wmma::mma_sync(fc[i][j], fah[i], fbl[j], fc[i][j]);
                        wmma::mma_sync(fc[i][j], fah[i], fbh[j], fc[i][j]);
                    }
            }
        }
    };

    const int nIter = K / BK;

    // prologue: prefetch tiles 0 and 1
    issue_cp(0, 0);
    __pipeline_commit();
    if (nIter > 1) issue_cp(1, BK);
    __pipeline_commit();

    for (int it = 0; it < nIter; it++) {
        __pipeline_wait_prior(1);   // tile `it` landed (groups <= it complete)
        __syncthreads();            // visible to all; stage (it+2)%3 free
        if (it + 2 < nIter) issue_cp((it + 2) % NSTAGE, (it + 2) * BK);
        __pipeline_commit();
        mma_stage(it % NSTAGE);
    }
    __pipeline_wait_prior(0);
    __syncthreads();   // all MMAs done before smem reuse for C tile

    // C tile via smem (reuse)
    #pragma unroll
    for (int i = 0; i < 2; i++)
        #pragma unroll
        for (int j = 0; j < 2; j++)
            wmma::store_matrix_sync(&smem[(wm + i*16) * LDC_S + wn + j*16],
                                    fc[i][j], LDC_S, wmma::mem_row_major);
    __syncthreads();

    #pragma unroll
    for (int it = 0; it < 32; it++) {
        int idx = tid + it * 256;
        int m   = idx >> 6;
        int n   = idx & 63;
        float acc = smem[m * LDC_S + n];
        size_t gi = (size_t)(m0 + m) * ldc + n0 + n;
        float o;
        if (EPI == EPI_NONE)        o = acc;
        else if (EPI == EPI_TANH)   o = tanhf(acc);
        else if (EPI == EPI_SILU)   o = acc / (1.0f + __expf(-acc));
        else if (EPI == EPI_SIGMOID) o = 1.0f / (1.0f + __expf(-acc));
        else if (EPI == EPI_RELUSQ) { float rv = fmaxf(acc, 0.0f); o = rv * rv; }
        else if (EPI == EPI_ADDC)   o = acc + aux1[gi];
        else if (EPI == EPI_MIX)    o = aux1[gi] + aux2[gi] * (vec1[n0 + n] + acc);
        else /* EPI_FFNOUT */       o = aux1[gi] + aux2[gi] * acc;
        C[gi] = o;
    }
}

// ---------------- ln + token-shift fuse (time mix) ----------------
__global__ void __launch_bounds__(256)
ln_mix1(const float* __restrict__ x, const float* __restrict__ state,
        const float* __restrict__ lnw, const float* __restrict__ lnb,
        const float* __restrict__ maa_x,
        float* __restrict__ xn_o, float* __restrict__ sx_o,
        float* __restrict__ xmix_o)
{
    int b = blockIdx.x;
    const float* xr = x + (size_t)b * EMB;
    float v[8]; float s = 0.f, sq = 0.f;
    #pragma unroll
    for (int i = 0; i < 8; i++) {
        v[i] = xr[threadIdx.x + i * 256];
        s += v[i]; sq += v[i] * v[i];
    }
    __shared__ float red[16];
    #pragma unroll
    for (int o = 16; o > 0; o >>= 1) {
        s  += __shfl_down_sync(0xffffffffu, s,  o);
        sq += __shfl_down_sync(0xffffffffu, sq, o);
    }
    int w = threadIdx.x >> 5;
    if ((threadIdx.x & 31) == 0) { red[w] = s; red[w + 8] = sq; }
    __syncthreads();
    if (threadIdx.x == 0) {
        float ts = 0.f, tq = 0.f;
        for (int i = 0; i < 8; i++) { ts += red[i]; tq += red[i + 8]; }
        red[0] = ts; red[8] = tq;
    }
    __syncthreads();
    float mu  = red[0] * (1.0f / EMB);
    float var = red[8] * (1.0f / EMB) - mu * mu;
    float rs  = rsqrtf(var + 1e-5f);
    const float* srow = state + ((size_t)b * SROWS + 1) * EMB;
    #pragma unroll
    for (int i = 0; i < 8; i++) {
        int e = threadIdx.x + i * 256;
        float xnv = (v[i] - mu) * rs * lnw[e] + lnb[e];
        float sxv = srow[e] - xnv;
        size_t gi = (size_t)b * EMB + e;
        xn_o[gi] = xnv;
        sx_o[gi] = sxv;
        xmix_o[gi] = xnv + sxv * maa_x[e];
    }
}

// ---------------- ln + token-shift fuse (channel mix) ----------------
__global__ void __launch_bounds__(256)
ln_mix2(const float* __restrict__ x1, const float* __restrict__ state,
        const float* __restrict__ lnw, const float* __restrict__ lnb,
        const float* __restrict__ maa_k, const float* __restrict__ maa_r,
        float* __restrict__ xk_o, float* __restrict__ xr_o)
{
    int b = blockIdx.x;
    const float* xr = x1 + (size_t)b * EMB;
    float v[8]; float s = 0.f, sq = 0.f;
    #pragma unroll
    for (int i = 0; i < 8; i++) {
        v[i] = xr[threadIdx.x + i * 256];
        s += v[i]; sq += v[i] * v[i];
    }
    __shared__ float red[16];
    #pragma unroll
    for (int o = 16; o > 0; o >>= 1) {
        s  += __shfl_down_sync(0xffffffffu, s,  o);
        sq += __shfl_down_sync(0xffffffffu, sq, o);
    }
    int w = threadIdx.x >> 5;
    if ((threadIdx.x & 31) == 0) { red[w] = s; red[w + 8] = sq; }
    __syncthreads();
    if (threadIdx.x == 0) {
        float ts = 0.f, tq = 0.f;
        for (int i = 0; i < 8; i++) { ts += red[i]; tq += red[i + 8]; }
        red[0] = ts; red[8] = tq;
    }
    __syncthreads();
    float mu  = red[0] * (1.0f / EMB);
    float var = red[8] * (1.0f / EMB) - mu * mu;
    float rs  = rsqrtf(var + 1e-5f);
    const float* srow = state + (size_t)b * SROWS * EMB;  // row 0
    #pragma unroll
    for (int i = 0; i < 8; i++) {
        int e = threadIdx.x + i * 256;
        float xnv = (v[i] - mu) * rs * lnw[e] + lnb[e];
        float sxv = srow[e] - xnv;
        size_t gi = (size_t)b * EMB + e;
        xk_o[gi] = xnv + sxv * maa_k[e];
        xr_o[gi] = xnv + sxv * maa_r[e];
    }
}

// ---------------- wkv readout + groupnorm + (pre-silu'ed) gate ----------------
__global__ void __launch_bounds__(64)
wkv_gn(const float* __restrict__ r, const float* __restrict__ k,
       const float* __restrict__ v, const float* __restrict__ gp,
       const float* __restrict__ state, const float* __restrict__ faaaa,
       const float* __restrict__ gnw, const float* __restrict__ gnb,
       float* __restrict__ z)
{
    int bh = blockIdx.x;
    int b  = bh >> 5;
    int h  = bh & 31;
    int j  = threadIdx.x;  // 0..63
    size_t off = (size_t)b * EMB + h * 64 + j;
    float rv = r[off], kv = k[off], vv = v[off];
    float fv = faaaa[h * 64 + j];

    __shared__ float rs_sh[64];
    __shared__ float red1[2];
    __shared__ float red2[4];
    rs_sh[j] = rv;

    float p = rv * fv * kv;
    #pragma unroll
    for (int o = 16; o > 0; o >>= 1) p += __shfl_down_sync(0xffffffffu, p, o);
    int w = j >> 5;
    if ((j & 31) == 0) red1[w] = p;
    __syncthreads();
    float coef = red1[0] + red1[1];

    const float* sb = state + ((size_t)b * SROWS + 2 + 2 * h) * EMB;
    float acc = 0.f;
    #pragma unroll
    for (int i = 0; i < 64; i++)
        acc += rs_sh[i] * sb[(i >> 5) * EMB + ((i & 31) << 6) + j];

    float y = coef * vv + acc;

    float s = y, sq = y * y;
    #pragma unroll
    for (int o = 16; o > 0; o >>= 1) {
        s  += __shfl_down_sync(0xffffffffu, s,  o);
        sq += __shfl_down_sync(0xffffffffu, sq, o);
    }
    if ((j & 31) == 0) { red2[w] = s; red2[2 + w] = sq; }
    __syncthreads();
    float mu  = (red2[0] + red2[1]) * (1.0f / 64.0f);
    float var = (red2[2] + red2[3]) * (1.0f / 64.0f) - mu * mu;
    float zn  = (y - mu) * rsqrtf(var + 1e-5f) * gnw[h * 64 + j] + gnb[h * 64 + j];
    // gp is ALREADY silu(xg@Wg.T) — do NOT re-apply silu.
    z[off] = zn * gp[off];
}

// ---------------- launch ----------------
extern "C" void kernel_launch(void* const* d_in, const int* in_sizes, int n_in,
                              void* d_out, int out_size)
{
    (void)in_sizes; (void)n_in; (void)out_size;
    const float* x       = (const float*)d_in[0];
    const float* state   = (const float*)d_in[1];
    const float* ln1_w   = (const float*)d_in[2];
    const float* ln1_b   = (const float*)d_in[3];
    const float* ln2_w   = (const float*)d_in[4];
    const float* ln2_b   = (const float*)d_in[5];
    const float* maa_x   = (const float*)d_in[6];
    const float* maa_k   = (const float*)d_in[8];
    const float* maa_v   = (const float*)d_in[9];
    const float* maa_r   = (const float*)d_in[10];
    const float* maa_g   = (const float*)d_in[11];
    const float* maa_w1  = (const float*)d_in[12];  // [E, 320]
    const float* maa_w2  = (const float*)d_in[13];  // [5, 64, E]
    const float* faaaa   = (const float*)d_in[17];  // [H, 64]
    const float* Wr      = (const float*)d_in[18];
    const float* Wk      = (const float*)d_in[19];
    const float* Wv      = (const float*)d_in[20];
    const float* Wo      = (const float*)d_in[21];
    const float* Wg      = (const float*)d_in[22];
    const float* gn_w    = (const float*)d_in[23];
    const float* gn_b    = (const float*)d_in[24];
    const float* f_maa_k = (const float*)d_in[25];
    const float* f_maa_r = (const float*)d_in[26];
    const float* ffn_Wk  = (const float*)d_in[27];
    const float* ffn_Wr  = (const float*)d_in[28];
    const float* ffn_Wv  = (const float*)d_in[29];
    float* out = (float*)d_out;

    cudaFuncSetAttribute(gemm_k<EPI_TANH,   false>, cudaFuncAttributeMaxDynamicSharedMemorySize, (int)SMEM_BYTES);
    cudaFuncSetAttribute(gemm_k<EPI_MIX,    false>, cudaFuncAttributeMaxDynamicSharedMemorySize, (int)SMEM_BYTES);
    cudaFuncSetAttribute(gemm_k<EPI_NONE,   true >, cudaFuncAttributeMaxDynamicSharedMemorySize, (int)SMEM_BYTES);
    cudaFuncSetAttribute(gemm_k<EPI_SILU,   true >, cudaFuncAttributeMaxDynamicSharedMemorySize, (int)SMEM_BYTES);
    cudaFuncSetAttribute(gemm_k<EPI_ADDC,   true >, cudaFuncAttributeMaxDynamicSharedMemorySize, (int)SMEM_BYTES);
    cudaFuncSetAttribute(gemm_k<EPI_SIGMOID,true >, cudaFuncAttributeMaxDynamicSharedMemorySize, (int)SMEM_BYTES);
    cudaFuncSetAttribute(gemm_k<EPI_RELUSQ, true >, cudaFuncAttributeMaxDynamicSharedMemorySize, (int)SMEM_BYTES);
    cudaFuncSetAttribute(gemm_k<EPI_FFNOUT, true >, cudaFuncAttributeMaxDynamicSharedMemorySize, (int)SMEM_BYTES);

    float* scr = nullptr;
    cudaGetSymbolAddress((void**)&scr, g_scr);
    auto S = [&](int i) { return scr + (size_t)i * BATCH * EMB; };
    float *xn = S(SL_XN), *sx = S(SL_SX), *xmix = S(SL_XMIX);
    float *xk = S(SL_XK), *xv = S(SL_XV), *xrb = S(SL_XR), *xg = S(SL_XG);
    float *rb = S(SL_R), *kb = S(SL_K), *vb = S(SL_V), *gb = S(SL_G);
    float *zb = S(SL_Z), *x1 = S(SL_X1);
    float *xk2 = S(SL_XK2), *xr2 = S(SL_XR2);
    float *rr = S(SL_RR), *kk = S(SL_KK), *tb = S(SL_T);

    dim3 blk(256);
    dim3 gE(EMB / BN, BATCH / BM);      // 32 x 8
    dim3 gT(320 / BN, BATCH / BM);      // 5 x 8

    ln_mix1<<<BATCH, blk>>>(x, state, ln1_w, ln1_b, maa_x, xn, sx, xmix);

    gemm_k<EPI_TANH, false><<<gT, blk, SMEM_BYTES>>>(xmix, EMB, maa_w1, 320, tb, 320,
                                         BATCH, 320, EMB, nullptr, nullptr, nullptr);

    gemm_k<EPI_MIX, false><<<gE, blk, SMEM_BYTES>>>(tb + 64*1, 320, maa_w2 + (size_t)1*64*EMB, EMB,
                                        xk, EMB, BATCH, EMB, 64, xn, sx, maa_k);
    gemm_k<EPI_MIX, false><<<gE, blk, SMEM_BYTES>>>(tb + 64*2, 320, maa_w2 + (size_t)2*64*EMB, EMB,
                                        xv, EMB, BATCH, EMB, 64, xn, sx, maa_v);
    gemm_k<EPI_MIX, false><<<gE, blk, SMEM_BYTES>>>(tb + 64*3, 320, maa_w2 + (size_t)3*64*EMB, EMB,
                                        xrb, EMB, BATCH, EMB, 64, xn, sx, maa_r);
    gemm_k<EPI_MIX, false><<<gE, blk, SMEM_BYTES>>>(tb + 64*4, 320, maa_w2 + (size_t)4*64*EMB, EMB,
                                        xg, EMB, BATCH, EMB, 64, xn, sx, maa_g);

    gemm_k<EPI_NONE, true><<<gE, blk, SMEM_BYTES>>>(xrb, EMB, Wr, EMB, rb, EMB,
                                        BATCH, EMB, EMB, nullptr, nullptr, nullptr);
    gemm_k<EPI_NONE, true><<<gE, blk, SMEM_BYTES>>>(xk, EMB, Wk, EMB, kb, EMB,
                                        BATCH, EMB, EMB, nullptr, nullptr, nullptr);
    gemm_k<EPI_NONE, true><<<gE, blk, SMEM_BYTES>>>(xv, EMB, Wv, EMB, vb, EMB,
                                        BATCH, EMB, EMB, nullptr, nullptr, nullptr);
    gemm_k<EPI_SILU, true><<<gE, blk, SMEM_BYTES>>>(xg, EMB, Wg, EMB, gb, EMB,
                                        BATCH, EMB, EMB, nullptr, nullptr, nullptr);

    wkv_gn<<<BATCH * NHEAD, 64>>>(rb, kb, vb, gb, state, faaaa, gn_w, gn_b, zb);

    gemm_k<EPI_ADDC, true><<<gE, blk, SMEM_BYTES>>>(zb, EMB, Wo, EMB, x1, EMB,
                                        BATCH, EMB, EMB, x, nullptr, nullptr);

    ln_mix2<<<BATCH, blk>>>(x1, state, ln2_w, ln2_b, f_maa_k, f_maa_r, xk2, xr2);
    gemm_k<EPI_SIGMOID, true><<<gE, blk, SMEM_BYTES>>>(xr2, EMB, ffn_Wr, EMB, rr, EMB,
                                           BATCH, EMB, EMB, nullptr, nullptr, nullptr);
    gemm_k<EPI_RELUSQ, true><<<gE, blk, SMEM_BYTES>>>(xk2, EMB, ffn_Wk, EMB, kk, EMB,
                                          BATCH, EMB, EMB, nullptr, nullptr, nullptr);
    gemm_k<EPI_FFNOUT, true><<<gE, blk, SMEM_BYTES>>>(kk, EMB, ffn_Wv, EMB, out, EMB,
                                          BATCH, EMB, EMB, x1, rr, nullptr);
}